// round 1
// baseline (speedup 1.0000x reference)
#include <cuda_runtime.h>
#include <cuda_bf16.h>

// Problem constants (from reference setup_inputs)
#define NN 50000
#define NE 800000
#define F0 256
#define F1 128
#define F2 128
#define F3 64

// ---------------- device scratch (static, allocation-free) ----------------
__device__ float g_deg[NN];
__device__ float g_dis[NN];
__device__ float g_selfn[NN];
__device__ int   g_count[NN];
__device__ int   g_rowptr[NN + 1];
__device__ int   g_cursor[NN];
__device__ int   g_col[NE];
__device__ float g_enorm[NE];
__device__ float g_h[NN * 128];    // GEMM output buffer
__device__ float g_agg[NN * 128];  // aggregate output buffer

// ---------------- graph preprocessing ----------------
__global__ void k_init() {
    int i = blockIdx.x * blockDim.x + threadIdx.x;
    if (i < NN) { g_deg[i] = 1.0f; g_count[i] = 0; }  // self-loop weight 1
}

__global__ void k_edge_deg(const int* __restrict__ ei, const float* __restrict__ ew) {
    int e = blockIdx.x * blockDim.x + threadIdx.x;
    if (e < NE) {
        int d = ei[NE + e];
        atomicAdd(&g_deg[d], ew[e]);
        atomicAdd(&g_count[d], 1);
    }
}

__global__ void k_dis() {
    int i = blockIdx.x * blockDim.x + threadIdx.x;
    if (i < NN) {
        float dg = g_deg[i];
        float dis = (dg > 0.0f) ? rsqrtf(dg) : 0.0f;
        g_dis[i] = dis;
        g_selfn[i] = dis * dis;
    }
}

// single-block scan: rowptr (inclusive shifted) + cursor (exclusive)
__global__ void __launch_bounds__(1024) k_scan() {
    __shared__ int s[1024];
    int tid = threadIdx.x;
    if (tid == 0) g_rowptr[0] = 0;
    int carry = 0;
    for (int base = 0; base < NN; base += 1024) {
        int i = base + tid;
        int v = (i < NN) ? g_count[i] : 0;
        s[tid] = v;
        __syncthreads();
        for (int off = 1; off < 1024; off <<= 1) {
            int t = (tid >= off) ? s[tid - off] : 0;
            __syncthreads();
            s[tid] += t;
            __syncthreads();
        }
        if (i < NN) {
            g_rowptr[i + 1] = carry + s[tid];
            g_cursor[i]     = carry + s[tid] - v;
        }
        int tot = s[1023];
        __syncthreads();
        carry += tot;
    }
}

__global__ void k_scatter(const int* __restrict__ ei, const float* __restrict__ ew) {
    int e = blockIdx.x * blockDim.x + threadIdx.x;
    if (e < NE) {
        int src = ei[e];
        int dst = ei[NE + e];
        int pos = atomicAdd(&g_cursor[dst], 1);
        g_col[pos]   = src;
        g_enorm[pos] = g_dis[src] * ew[e] * g_dis[dst];
    }
}

// ---------------- tiled SMEM fp32 GEMM: C[M,FOUT] = A[M,FIN] @ W[FIN,FOUT] ----
template <int FIN, int FOUT>
__global__ void __launch_bounds__(256) gemm_k(const float* __restrict__ A,
                                              const float* __restrict__ W,
                                              float* __restrict__ C, int M) {
    constexpr int BM = 64, BK = 16;
    constexpr int TN = FOUT / 32;  // 4 or 2
    __shared__ float As[BK][BM + 4];  // transposed, padded for alignment
    __shared__ float Bs[BK][FOUT];

    int tid = threadIdx.x;
    int tx = tid & 31, ty = tid >> 5;
    int rowBase = blockIdx.x * BM;

    float acc[8][TN];
#pragma unroll
    for (int r = 0; r < 8; r++)
#pragma unroll
        for (int c = 0; c < TN; c++) acc[r][c] = 0.0f;

    for (int kt = 0; kt < FIN; kt += BK) {
        // A tile: 64x16 floats = 256 float4, one per thread, stored transposed
        {
            int r = tid >> 2;       // 0..63
            int kq = tid & 3;       // 0..3
            int grow = rowBase + r;
            float4 v = make_float4(0.f, 0.f, 0.f, 0.f);
            if (grow < M) v = *(const float4*)&A[grow * FIN + kt + kq * 4];
            As[kq * 4 + 0][r] = v.x;
            As[kq * 4 + 1][r] = v.y;
            As[kq * 4 + 2][r] = v.z;
            As[kq * 4 + 3][r] = v.w;
        }
        // B tile: 16 x FOUT via float4, coalesced
        {
            constexpr int NV = (BK * FOUT / 4) / 256;  // 2 (FOUT=128) or 1 (FOUT=64)
#pragma unroll
            for (int l = 0; l < NV; l++) {
                int lin = tid + l * 256;
                int r = lin / (FOUT / 4);
                int c = (lin % (FOUT / 4)) * 4;
                *(float4*)&Bs[r][c] = *(const float4*)&W[(kt + r) * FOUT + c];
            }
        }
        __syncthreads();
#pragma unroll
        for (int k = 0; k < BK; k++) {
            float4 a0 = *(float4*)&As[k][ty * 8];
            float4 a1 = *(float4*)&As[k][ty * 8 + 4];
            float a[8] = {a0.x, a0.y, a0.z, a0.w, a1.x, a1.y, a1.z, a1.w};
            float b[TN];
            if constexpr (TN == 4) {
                float4 bv = *(float4*)&Bs[k][tx * 4];
                b[0] = bv.x; b[1] = bv.y; b[2] = bv.z; b[3] = bv.w;
            } else {
                float2 bv = *(float2*)&Bs[k][tx * 2];
                b[0] = bv.x; b[1] = bv.y;
            }
#pragma unroll
            for (int r = 0; r < 8; r++)
#pragma unroll
                for (int c = 0; c < TN; c++) acc[r][c] = fmaf(a[r], b[c], acc[r][c]);
        }
        __syncthreads();
    }

#pragma unroll
    for (int r = 0; r < 8; r++) {
        int grow = rowBase + ty * 8 + r;
        if (grow < M) {
            if constexpr (TN == 4) {
                float4 v = make_float4(acc[r][0], acc[r][1], acc[r][2], acc[r][3]);
                *(float4*)&C[grow * FOUT + tx * 4] = v;
            } else {
                float2 v = make_float2(acc[r][0], acc[r][1]);
                *(float2*)&C[grow * FOUT + tx * 2] = v;
            }
        }
    }
}

// ---------------- CSR aggregation: one warp per destination node ----------
template <int F, bool RELU>
__global__ void __launch_bounds__(256) agg_k(const float* __restrict__ h,
                                             const float* __restrict__ bias,
                                             float* __restrict__ out) {
    constexpr int TF = F / 32;
    int gw = (blockIdx.x * blockDim.x + threadIdx.x) >> 5;
    int lane = threadIdx.x & 31;
    if (gw >= NN) return;

    float acc[TF];
    float sn = g_selfn[gw];
#pragma unroll
    for (int j = 0; j < TF; j++) acc[j] = sn * h[gw * F + j * 32 + lane];

    int beg = g_rowptr[gw];
    int end = g_rowptr[gw + 1];
    for (int e = beg; e < end; e++) {
        int s = g_col[e];
        float w = g_enorm[e];
        const float* hp = h + s * F + lane;
#pragma unroll
        for (int j = 0; j < TF; j++) acc[j] = fmaf(w, __ldg(hp + j * 32), acc[j]);
    }

#pragma unroll
    for (int j = 0; j < TF; j++) {
        float v = acc[j] + bias[j * 32 + lane];
        if (RELU) v = fmaxf(v, 0.0f);
        out[gw * F + j * 32 + lane] = v;
    }
}

// ---------------- launch ----------------
extern "C" void kernel_launch(void* const* d_in, const int* in_sizes, int n_in,
                              void* d_out, int out_size) {
    const float* x  = (const float*)d_in[0];
    const int*   ei = (const int*)  d_in[1];
    const float* ew = (const float*)d_in[2];
    const float* W1 = (const float*)d_in[3];
    const float* b1 = (const float*)d_in[4];
    const float* W2 = (const float*)d_in[5];
    const float* b2 = (const float*)d_in[6];
    const float* W3 = (const float*)d_in[7];
    const float* b3 = (const float*)d_in[8];
    float* out = (float*)d_out;

    void *ph = nullptr, *pagg = nullptr;
    cudaGetSymbolAddress(&ph, g_h);
    cudaGetSymbolAddress(&pagg, g_agg);
    float* h   = (float*)ph;
    float* agg = (float*)pagg;

    const int nodeBlocks = (NN + 255) / 256;
    const int edgeBlocks = (NE + 255) / 256;
    const int gemmBlocks = (NN + 63) / 64;
    const int aggBlocks  = (NN + 7) / 8;  // 8 warps per 256-thread block

    // CSR build
    k_init<<<nodeBlocks, 256>>>();
    k_edge_deg<<<edgeBlocks, 256>>>(ei, ew);
    k_dis<<<nodeBlocks, 256>>>();
    k_scan<<<1, 1024>>>();
    k_scatter<<<edgeBlocks, 256>>>(ei, ew);

    // Layer 1: 256 -> 128, relu
    gemm_k<F0, F1><<<gemmBlocks, 256>>>(x, W1, h, NN);
    agg_k<F1, true><<<aggBlocks, 256>>>(h, b1, agg);

    // Layer 2: 128 -> 128, relu
    gemm_k<F1, F2><<<gemmBlocks, 256>>>(agg, W2, h, NN);
    agg_k<F2, true><<<aggBlocks, 256>>>(h, b2, agg);

    // Layer 3: 128 -> 64, no relu, write d_out
    gemm_k<F2, F3><<<gemmBlocks, 256>>>(agg, W3, h, NN);
    agg_k<F3, false><<<aggBlocks, 256>>>(h, b3, out);
}

// round 2
// speedup vs baseline: 1.0096x; 1.0096x over previous
#include <cuda_runtime.h>
#include <cuda_bf16.h>

// Problem constants (from reference setup_inputs)
#define NN 50000
#define NE 800000
#define F0 256
#define F1 128
#define F2 128
#define F3 64

// ---------------- device scratch (static, allocation-free) ----------------
__device__ float g_deg[NN];
__device__ float g_dis[NN];
__device__ float g_selfn[NN];
__device__ int   g_count[NN];
__device__ int   g_rowptr[NN + 1];
__device__ int   g_cursor[NN];
__device__ int   g_col[NE];
__device__ float g_enorm[NE];
__device__ float g_h[NN * 128];    // GEMM output buffer
__device__ float g_agg[NN * 128];  // aggregate output buffer

// ---------------- graph preprocessing ----------------
__global__ void k_init() {
    int i = blockIdx.x * blockDim.x + threadIdx.x;
    if (i < NN) { g_deg[i] = 1.0f; g_count[i] = 0; }  // self-loop weight 1
}

__global__ void k_edge_deg(const int* __restrict__ ei, const float* __restrict__ ew) {
    int e = blockIdx.x * blockDim.x + threadIdx.x;
    if (e < NE) {
        int d = ei[NE + e];
        atomicAdd(&g_deg[d], ew[e]);
        atomicAdd(&g_count[d], 1);
    }
}

__global__ void k_dis() {
    int i = blockIdx.x * blockDim.x + threadIdx.x;
    if (i < NN) {
        float dg = g_deg[i];
        float dis = (dg > 0.0f) ? rsqrtf(dg) : 0.0f;
        g_dis[i] = dis;
        g_selfn[i] = dis * dis;
    }
}

// Single-block, single-pass scan: 1024 threads, each owns a contiguous chunk.
// Pass 1: chunk sums. Shuffle scan across threads (2 barriers). Pass 2: write
// exclusive prefixes. Writes g_rowptr[i] = excl_prefix(i), g_rowptr[NN]=total,
// g_cursor[i] = excl_prefix(i).
__global__ void __launch_bounds__(1024) k_scan() {
    constexpr int CHUNK = (NN + 1023) / 1024;  // 49
    int tid = threadIdx.x;
    int lane = tid & 31, wid = tid >> 5;
    int base = tid * CHUNK;

    // pass 1: chunk sum
    int sum = 0;
#pragma unroll 7
    for (int j = 0; j < CHUNK; j++) {
        int i = base + j;
        if (i < NN) sum += g_count[i];
    }

    // warp inclusive scan of chunk sums
    int inc = sum;
#pragma unroll
    for (int off = 1; off < 32; off <<= 1) {
        int t = __shfl_up_sync(0xFFFFFFFFu, inc, off);
        if (lane >= off) inc += t;
    }
    __shared__ int wsum[32];
    if (lane == 31) wsum[wid] = inc;
    __syncthreads();
    if (wid == 0) {
        int v = wsum[lane];
#pragma unroll
        for (int off = 1; off < 32; off <<= 1) {
            int t = __shfl_up_sync(0xFFFFFFFFu, v, off);
            if (lane >= off) v += t;
        }
        wsum[lane] = v;
    }
    __syncthreads();
    int warpPrefix = (wid > 0) ? wsum[wid - 1] : 0;
    int threadBase = warpPrefix + inc - sum;  // exclusive prefix of this thread's chunk
    if (tid == 0) g_rowptr[NN] = wsum[31];    // total

    // pass 2: per-element exclusive prefix
    int run = threadBase;
#pragma unroll 7
    for (int j = 0; j < CHUNK; j++) {
        int i = base + j;
        if (i < NN) {
            g_rowptr[i] = run;
            g_cursor[i] = run;
            run += g_count[i];
        }
    }
}

__global__ void k_scatter(const int* __restrict__ ei, const float* __restrict__ ew) {
    int e = blockIdx.x * blockDim.x + threadIdx.x;
    if (e < NE) {
        int src = ei[e];
        int dst = ei[NE + e];
        int pos = atomicAdd(&g_cursor[dst], 1);
        g_col[pos]   = src;
        g_enorm[pos] = g_dis[src] * ew[e] * g_dis[dst];
    }
}

// ---------------- tiled SMEM fp32 GEMM: C[M,FOUT] = A[M,FIN] @ W[FIN,FOUT] ----
template <int FIN, int FOUT>
__global__ void __launch_bounds__(256) gemm_k(const float* __restrict__ A,
                                              const float* __restrict__ W,
                                              float* __restrict__ C, int M) {
    constexpr int BM = 64, BK = 16;
    constexpr int TN = FOUT / 32;  // 4 or 2
    __shared__ float As[BK][BM + 4];  // transposed, padded for alignment
    __shared__ float Bs[BK][FOUT];

    int tid = threadIdx.x;
    int tx = tid & 31, ty = tid >> 5;
    int rowBase = blockIdx.x * BM;

    float acc[8][TN];
#pragma unroll
    for (int r = 0; r < 8; r++)
#pragma unroll
        for (int c = 0; c < TN; c++) acc[r][c] = 0.0f;

    for (int kt = 0; kt < FIN; kt += BK) {
        // A tile: 64x16 floats = 256 float4, one per thread, stored transposed
        {
            int r = tid >> 2;       // 0..63
            int kq = tid & 3;       // 0..3
            int grow = rowBase + r;
            float4 v = make_float4(0.f, 0.f, 0.f, 0.f);
            if (grow < M) v = *(const float4*)&A[grow * FIN + kt + kq * 4];
            As[kq * 4 + 0][r] = v.x;
            As[kq * 4 + 1][r] = v.y;
            As[kq * 4 + 2][r] = v.z;
            As[kq * 4 + 3][r] = v.w;
        }
        // B tile: 16 x FOUT via float4, coalesced
        {
            constexpr int NV = (BK * FOUT / 4) / 256;  // 2 (FOUT=128) or 1 (FOUT=64)
#pragma unroll
            for (int l = 0; l < NV; l++) {
                int lin = tid + l * 256;
                int r = lin / (FOUT / 4);
                int c = (lin % (FOUT / 4)) * 4;
                *(float4*)&Bs[r][c] = *(const float4*)&W[(kt + r) * FOUT + c];
            }
        }
        __syncthreads();
#pragma unroll
        for (int k = 0; k < BK; k++) {
            float4 a0 = *(float4*)&As[k][ty * 8];
            float4 a1 = *(float4*)&As[k][ty * 8 + 4];
            float a[8] = {a0.x, a0.y, a0.z, a0.w, a1.x, a1.y, a1.z, a1.w};
            float b[TN];
            if constexpr (TN == 4) {
                float4 bv = *(float4*)&Bs[k][tx * 4];
                b[0] = bv.x; b[1] = bv.y; b[2] = bv.z; b[3] = bv.w;
            } else {
                float2 bv = *(float2*)&Bs[k][tx * 2];
                b[0] = bv.x; b[1] = bv.y;
            }
#pragma unroll
            for (int r = 0; r < 8; r++)
#pragma unroll
                for (int c = 0; c < TN; c++) acc[r][c] = fmaf(a[r], b[c], acc[r][c]);
        }
        __syncthreads();
    }

#pragma unroll
    for (int r = 0; r < 8; r++) {
        int grow = rowBase + ty * 8 + r;
        if (grow < M) {
            if constexpr (TN == 4) {
                float4 v = make_float4(acc[r][0], acc[r][1], acc[r][2], acc[r][3]);
                *(float4*)&C[grow * FOUT + tx * 4] = v;
            } else {
                float2 v = make_float2(acc[r][0], acc[r][1]);
                *(float2*)&C[grow * FOUT + tx * 2] = v;
            }
        }
    }
}

// ---------------- CSR aggregation: one warp per destination node ----------
template <int F, bool RELU>
__global__ void __launch_bounds__(256) agg_k(const float* __restrict__ h,
                                             const float* __restrict__ bias,
                                             float* __restrict__ out) {
    constexpr int TF = F / 32;
    int gw = (blockIdx.x * blockDim.x + threadIdx.x) >> 5;
    int lane = threadIdx.x & 31;
    if (gw >= NN) return;

    float acc[TF];
    float sn = g_selfn[gw];
#pragma unroll
    for (int j = 0; j < TF; j++) acc[j] = sn * h[gw * F + j * 32 + lane];

    int beg = g_rowptr[gw];
    int end = g_rowptr[gw + 1];
    for (int e = beg; e < end; e++) {
        int s = g_col[e];
        float w = g_enorm[e];
        const float* hp = h + s * F + lane;
#pragma unroll
        for (int j = 0; j < TF; j++) acc[j] = fmaf(w, __ldg(hp + j * 32), acc[j]);
    }

#pragma unroll
    for (int j = 0; j < TF; j++) {
        float v = acc[j] + bias[j * 32 + lane];
        if (RELU) v = fmaxf(v, 0.0f);
        out[gw * F + j * 32 + lane] = v;
    }
}

// ---------------- launch ----------------
extern "C" void kernel_launch(void* const* d_in, const int* in_sizes, int n_in,
                              void* d_out, int out_size) {
    const float* x  = (const float*)d_in[0];
    const int*   ei = (const int*)  d_in[1];
    const float* ew = (const float*)d_in[2];
    const float* W1 = (const float*)d_in[3];
    const float* b1 = (const float*)d_in[4];
    const float* W2 = (const float*)d_in[5];
    const float* b2 = (const float*)d_in[6];
    const float* W3 = (const float*)d_in[7];
    const float* b3 = (const float*)d_in[8];
    float* out = (float*)d_out;

    void *ph = nullptr, *pagg = nullptr;
    cudaGetSymbolAddress(&ph, g_h);
    cudaGetSymbolAddress(&pagg, g_agg);
    float* h   = (float*)ph;
    float* agg = (float*)pagg;

    const int nodeBlocks = (NN + 255) / 256;
    const int edgeBlocks = (NE + 255) / 256;
    const int gemmBlocks = (NN + 63) / 64;
    const int aggBlocks  = (NN + 7) / 8;  // 8 warps per 256-thread block

    // CSR build
    k_init<<<nodeBlocks, 256>>>();
    k_edge_deg<<<edgeBlocks, 256>>>(ei, ew);
    k_dis<<<nodeBlocks, 256>>>();
    k_scan<<<1, 1024>>>();
    k_scatter<<<edgeBlocks, 256>>>(ei, ew);

    // Layer 1: 256 -> 128, relu
    gemm_k<F0, F1><<<gemmBlocks, 256>>>(x, W1, h, NN);
    agg_k<F1, true><<<aggBlocks, 256>>>(h, b1, agg);

    // Layer 2: 128 -> 128, relu
    gemm_k<F1, F2><<<gemmBlocks, 256>>>(agg, W2, h, NN);
    agg_k<F2, true><<<aggBlocks, 256>>>(h, b2, agg);

    // Layer 3: 128 -> 64, no relu, write d_out
    gemm_k<F2, F3><<<gemmBlocks, 256>>>(agg, W3, h, NN);
    agg_k<F3, false><<<aggBlocks, 256>>>(h, b3, out);
}

// round 3
// speedup vs baseline: 1.2635x; 1.2515x over previous
#include <cuda_runtime.h>
#include <cuda_bf16.h>

// Problem constants (from reference setup_inputs)
#define NN 50000
#define NE 800000
#define F0 256
#define F1 128
#define F2 128
#define F3 64

#define SCAN_B 256
#define SCAN_G ((NN + SCAN_B - 1) / SCAN_B)   // 196

// ---------------- device scratch (static, allocation-free) ----------------
__device__ float g_deg[NN];
__device__ float g_dis[NN];
__device__ float g_selfn[NN];
__device__ int   g_count[NN];
__device__ int   g_rowptr[NN + 1];
__device__ int   g_cursor[NN];
__device__ int   g_bsum[SCAN_G];
__device__ int   g_bpre[SCAN_G];
__device__ int   g_col[NE];
__device__ float g_enorm[NE];
__device__ float g_h[NN * 128];    // GEMM output buffer
__device__ float g_agg[NN * 128];  // aggregate output buffer

// ---------------- graph preprocessing ----------------
__global__ void k_init() {
    int i = blockIdx.x * blockDim.x + threadIdx.x;
    if (i < NN) { g_deg[i] = 1.0f; g_count[i] = 0; }  // self-loop weight 1
}

__global__ void k_edge_deg(const int* __restrict__ ei, const float* __restrict__ ew) {
    int e = blockIdx.x * blockDim.x + threadIdx.x;
    if (e < NE) {
        int d = ei[NE + e];
        atomicAdd(&g_deg[d], ew[e]);
        atomicAdd(&g_count[d], 1);
    }
}

__global__ void k_dis() {
    int i = blockIdx.x * blockDim.x + threadIdx.x;
    if (i < NN) {
        float dg = g_deg[i];
        float dis = (dg > 0.0f) ? rsqrtf(dg) : 0.0f;
        g_dis[i] = dis;
        g_selfn[i] = dis * dis;
    }
}

// ---- coalesced 3-kernel scan ----
// 1) per-block sums
__global__ void __launch_bounds__(SCAN_B) k_blocksum() {
    int i = blockIdx.x * SCAN_B + threadIdx.x;
    int lane = threadIdx.x & 31, wid = threadIdx.x >> 5;
    int v = (i < NN) ? g_count[i] : 0;
    int s = v;
#pragma unroll
    for (int off = 16; off > 0; off >>= 1) s += __shfl_down_sync(0xFFFFFFFFu, s, off);
    __shared__ int ws[8];
    if (lane == 0) ws[wid] = s;
    __syncthreads();
    if (threadIdx.x == 0) {
        int t = 0;
#pragma unroll
        for (int w = 0; w < 8; w++) t += ws[w];
        g_bsum[blockIdx.x] = t;
    }
}

// 2) scan the block sums (single block)
__global__ void __launch_bounds__(SCAN_B) k_scanbsum() {
    int tid = threadIdx.x;
    int lane = tid & 31, wid = tid >> 5;
    int v = (tid < SCAN_G) ? g_bsum[tid] : 0;
    int inc = v;
#pragma unroll
    for (int off = 1; off < 32; off <<= 1) {
        int t = __shfl_up_sync(0xFFFFFFFFu, inc, off);
        if (lane >= off) inc += t;
    }
    __shared__ int ws[8];
    if (lane == 31) ws[wid] = inc;
    __syncthreads();
    if (wid == 0 && lane < 8) {
        int x = ws[lane];
#pragma unroll
        for (int off = 1; off < 8; off <<= 1) {
            int t = __shfl_up_sync(0xFFu, x, off);
            if (lane >= off) x += t;
        }
        ws[lane] = x;
    }
    __syncthreads();
    int warpPre = (wid > 0) ? ws[wid - 1] : 0;
    if (tid < SCAN_G) g_bpre[tid] = warpPre + inc - v;  // exclusive prefix
    if (tid == 0) g_rowptr[NN] = ws[7];                  // total
}

// 3) per-element exclusive prefixes (coalesced)
__global__ void __launch_bounds__(SCAN_B) k_writepre() {
    int i = blockIdx.x * SCAN_B + threadIdx.x;
    int lane = threadIdx.x & 31, wid = threadIdx.x >> 5;
    int v = (i < NN) ? g_count[i] : 0;
    int inc = v;
#pragma unroll
    for (int off = 1; off < 32; off <<= 1) {
        int t = __shfl_up_sync(0xFFFFFFFFu, inc, off);
        if (lane >= off) inc += t;
    }
    __shared__ int ws[8];
    if (lane == 31) ws[wid] = inc;
    __syncthreads();
    if (wid == 0 && lane < 8) {
        int x = ws[lane];
#pragma unroll
        for (int off = 1; off < 8; off <<= 1) {
            int t = __shfl_up_sync(0xFFu, x, off);
            if (lane >= off) x += t;
        }
        ws[lane] = x;
    }
    __syncthreads();
    int warpPre = (wid > 0) ? ws[wid - 1] : 0;
    if (i < NN) {
        int excl = g_bpre[blockIdx.x] + warpPre + inc - v;
        g_rowptr[i] = excl;
        g_cursor[i] = excl;
    }
}

__global__ void k_scatter(const int* __restrict__ ei, const float* __restrict__ ew) {
    int e = blockIdx.x * blockDim.x + threadIdx.x;
    if (e < NE) {
        int src = ei[e];
        int dst = ei[NE + e];
        int pos = atomicAdd(&g_cursor[dst], 1);
        g_col[pos]   = src;
        g_enorm[pos] = g_dis[src] * ew[e] * g_dis[dst];
    }
}

// ---------------- tiled SMEM fp32 GEMM: C[M,FOUT] = A[M,FIN] @ W[FIN,FOUT] ----
template <int FIN, int FOUT>
__global__ void __launch_bounds__(256) gemm_k(const float* __restrict__ A,
                                              const float* __restrict__ W,
                                              float* __restrict__ C, int M) {
    constexpr int BM = 64, BK = 16;
    constexpr int TN = FOUT / 32;  // 4 or 2
    __shared__ float As[BK][BM + 4];  // transposed, padded for alignment
    __shared__ float Bs[BK][FOUT];

    int tid = threadIdx.x;
    int tx = tid & 31, ty = tid >> 5;
    int rowBase = blockIdx.x * BM;

    float acc[8][TN];
#pragma unroll
    for (int r = 0; r < 8; r++)
#pragma unroll
        for (int c = 0; c < TN; c++) acc[r][c] = 0.0f;

    for (int kt = 0; kt < FIN; kt += BK) {
        // A tile: 64x16 floats = 256 float4, one per thread, stored transposed
        {
            int r = tid >> 2;       // 0..63
            int kq = tid & 3;       // 0..3
            int grow = rowBase + r;
            float4 v = make_float4(0.f, 0.f, 0.f, 0.f);
            if (grow < M) v = *(const float4*)&A[grow * FIN + kt + kq * 4];
            As[kq * 4 + 0][r] = v.x;
            As[kq * 4 + 1][r] = v.y;
            As[kq * 4 + 2][r] = v.z;
            As[kq * 4 + 3][r] = v.w;
        }
        // B tile: 16 x FOUT via float4, coalesced
        {
            constexpr int NV = (BK * FOUT / 4) / 256;  // 2 (FOUT=128) or 1 (FOUT=64)
#pragma unroll
            for (int l = 0; l < NV; l++) {
                int lin = tid + l * 256;
                int r = lin / (FOUT / 4);
                int c = (lin % (FOUT / 4)) * 4;
                *(float4*)&Bs[r][c] = *(const float4*)&W[(kt + r) * FOUT + c];
            }
        }
        __syncthreads();
#pragma unroll
        for (int k = 0; k < BK; k++) {
            float4 a0 = *(float4*)&As[k][ty * 8];
            float4 a1 = *(float4*)&As[k][ty * 8 + 4];
            float a[8] = {a0.x, a0.y, a0.z, a0.w, a1.x, a1.y, a1.z, a1.w};
            float b[TN];
            if constexpr (TN == 4) {
                float4 bv = *(float4*)&Bs[k][tx * 4];
                b[0] = bv.x; b[1] = bv.y; b[2] = bv.z; b[3] = bv.w;
            } else {
                float2 bv = *(float2*)&Bs[k][tx * 2];
                b[0] = bv.x; b[1] = bv.y;
            }
#pragma unroll
            for (int r = 0; r < 8; r++)
#pragma unroll
                for (int c = 0; c < TN; c++) acc[r][c] = fmaf(a[r], b[c], acc[r][c]);
        }
        __syncthreads();
    }

#pragma unroll
    for (int r = 0; r < 8; r++) {
        int grow = rowBase + ty * 8 + r;
        if (grow < M) {
            if constexpr (TN == 4) {
                float4 v = make_float4(acc[r][0], acc[r][1], acc[r][2], acc[r][3]);
                *(float4*)&C[grow * FOUT + tx * 4] = v;
            } else {
                float2 v = make_float2(acc[r][0], acc[r][1]);
                *(float2*)&C[grow * FOUT + tx * 2] = v;
            }
        }
    }
}

// ---------------- CSR aggregation: one warp per destination node ----------
template <int F, bool RELU>
__global__ void __launch_bounds__(256) agg_k(const float* __restrict__ h,
                                             const float* __restrict__ bias,
                                             float* __restrict__ out) {
    constexpr int TF = F / 32;
    int gw = (blockIdx.x * blockDim.x + threadIdx.x) >> 5;
    int lane = threadIdx.x & 31;
    if (gw >= NN) return;

    float acc[TF];
    float sn = g_selfn[gw];
#pragma unroll
    for (int j = 0; j < TF; j++) acc[j] = sn * h[gw * F + j * 32 + lane];

    int beg = g_rowptr[gw];
    int end = g_rowptr[gw + 1];
    for (int e = beg; e < end; e++) {
        int s = g_col[e];
        float w = g_enorm[e];
        const float* hp = h + s * F + lane;
#pragma unroll
        for (int j = 0; j < TF; j++) acc[j] = fmaf(w, __ldg(hp + j * 32), acc[j]);
    }

#pragma unroll
    for (int j = 0; j < TF; j++) {
        float v = acc[j] + bias[j * 32 + lane];
        if (RELU) v = fmaxf(v, 0.0f);
        out[gw * F + j * 32 + lane] = v;
    }
}

// ---------------- launch ----------------
extern "C" void kernel_launch(void* const* d_in, const int* in_sizes, int n_in,
                              void* d_out, int out_size) {
    const float* x  = (const float*)d_in[0];
    const int*   ei = (const int*)  d_in[1];
    const float* ew = (const float*)d_in[2];
    const float* W1 = (const float*)d_in[3];
    const float* b1 = (const float*)d_in[4];
    const float* W2 = (const float*)d_in[5];
    const float* b2 = (const float*)d_in[6];
    const float* W3 = (const float*)d_in[7];
    const float* b3 = (const float*)d_in[8];
    float* out = (float*)d_out;

    void *ph = nullptr, *pagg = nullptr;
    cudaGetSymbolAddress(&ph, g_h);
    cudaGetSymbolAddress(&pagg, g_agg);
    float* h   = (float*)ph;
    float* agg = (float*)pagg;

    const int nodeBlocks = (NN + 255) / 256;
    const int edgeBlocks = (NE + 255) / 256;
    const int gemmBlocks = (NN + 63) / 64;
    const int aggBlocks  = (NN + 7) / 8;  // 8 warps per 256-thread block

    // CSR build
    k_init<<<nodeBlocks, 256>>>();
    k_edge_deg<<<edgeBlocks, 256>>>(ei, ew);
    k_dis<<<nodeBlocks, 256>>>();
    k_blocksum<<<SCAN_G, SCAN_B>>>();
    k_scanbsum<<<1, SCAN_B>>>();
    k_writepre<<<SCAN_G, SCAN_B>>>();
    k_scatter<<<edgeBlocks, 256>>>(ei, ew);

    // Layer 1: 256 -> 128, relu
    gemm_k<F0, F1><<<gemmBlocks, 256>>>(x, W1, h, NN);
    agg_k<F1, true><<<aggBlocks, 256>>>(h, b1, agg);

    // Layer 2: 128 -> 128, relu
    gemm_k<F1, F2><<<gemmBlocks, 256>>>(agg, W2, h, NN);
    agg_k<F2, true><<<aggBlocks, 256>>>(h, b2, agg);

    // Layer 3: 128 -> 64, no relu, write d_out
    gemm_k<F2, F3><<<gemmBlocks, 256>>>(agg, W3, h, NN);
    agg_k<F3, false><<<aggBlocks, 256>>>(h, b3, out);
}

// round 7
// speedup vs baseline: 1.3752x; 1.0884x over previous
#include <cuda_runtime.h>
#include <cuda_bf16.h>
#include <cstdint>

// Problem constants (from reference setup_inputs)
#define NN 50000
#define NE 800000
#define F0 256
#define F1 128
#define F2 128
#define F3 64

#define SCAN_B 256
#define SCAN_G ((NN + SCAN_B - 1) / SCAN_B)   // 196

// ---------------- device scratch (static, allocation-free) ----------------
__device__ float g_deg[NN];
__device__ float g_dis[NN];
__device__ float g_selfn[NN];
__device__ int   g_count[NN];
__device__ int   g_rowptr[NN + 1];
__device__ int   g_cursor[NN];
__device__ int   g_bsum[SCAN_G];
__device__ int   g_bpre[SCAN_G];
__device__ int   g_col[NE];
__device__ float g_enorm[NE];
__device__ float g_h[NN * 128];                  // GEMM output (fp32, agg input)
__device__ __nv_bfloat16 g_xhi[NN * F0];         // split input features
__device__ __nv_bfloat16 g_xlo[NN * F0];
__device__ __nv_bfloat16 g_ahi[NN * 128];        // split agg outputs (layers 1,2)
__device__ __nv_bfloat16 g_alo[NN * 128];
// transposed split weights: W1t [128][256] @0, W2t [128][128] @32768, W3t [64][128] @49152
#define W1T_OFF 0
#define W2T_OFF (128 * 256)
#define W3T_OFF (128 * 256 + 128 * 128)
__device__ __nv_bfloat16 g_whi[128 * 256 + 128 * 128 + 64 * 128];
__device__ __nv_bfloat16 g_wlo[128 * 256 + 128 * 128 + 64 * 128];

// ---------------- helpers ----------------
__device__ __forceinline__ void splitf(float v, __nv_bfloat16& h, __nv_bfloat16& l) {
    h = __float2bfloat16(v);
    l = __float2bfloat16(v - __bfloat162float(h));
}

__device__ __forceinline__ void mma_bf16(float* c, const uint32_t* a, const uint32_t* b) {
    asm volatile(
        "mma.sync.aligned.m16n8k16.row.col.f32.bf16.bf16.f32 "
        "{%0,%1,%2,%3}, {%4,%5,%6,%7}, {%8,%9}, {%0,%1,%2,%3};"
        : "+f"(c[0]), "+f"(c[1]), "+f"(c[2]), "+f"(c[3])
        : "r"(a[0]), "r"(a[1]), "r"(a[2]), "r"(a[3]), "r"(b[0]), "r"(b[1]));
}

// ---------------- graph preprocessing ----------------
__global__ void k_init() {
    int i = blockIdx.x * blockDim.x + threadIdx.x;
    if (i < NN) { g_deg[i] = 1.0f; g_count[i] = 0; }  // self-loop weight 1
}

__global__ void k_edge_deg(const int* __restrict__ ei, const float* __restrict__ ew) {
    int e = blockIdx.x * blockDim.x + threadIdx.x;
    if (e < NE) {
        int d = ei[NE + e];
        atomicAdd(&g_deg[d], ew[e]);
        atomicAdd(&g_count[d], 1);
    }
}

__global__ void k_dis() {
    int i = blockIdx.x * blockDim.x + threadIdx.x;
    if (i < NN) {
        float dg = g_deg[i];
        float dis = (dg > 0.0f) ? rsqrtf(dg) : 0.0f;
        g_dis[i] = dis;
        g_selfn[i] = dis * dis;
    }
}

// ---- coalesced 3-kernel scan ----
__global__ void __launch_bounds__(SCAN_B) k_blocksum() {
    int i = blockIdx.x * SCAN_B + threadIdx.x;
    int lane = threadIdx.x & 31, wid = threadIdx.x >> 5;
    int v = (i < NN) ? g_count[i] : 0;
    int s = v;
#pragma unroll
    for (int off = 16; off > 0; off >>= 1) s += __shfl_down_sync(0xFFFFFFFFu, s, off);
    __shared__ int ws[8];
    if (lane == 0) ws[wid] = s;
    __syncthreads();
    if (threadIdx.x == 0) {
        int t = 0;
#pragma unroll
        for (int w = 0; w < 8; w++) t += ws[w];
        g_bsum[blockIdx.x] = t;
    }
}

__global__ void __launch_bounds__(SCAN_B) k_scanbsum() {
    int tid = threadIdx.x;
    int lane = tid & 31, wid = tid >> 5;
    int v = (tid < SCAN_G) ? g_bsum[tid] : 0;
    int inc = v;
#pragma unroll
    for (int off = 1; off < 32; off <<= 1) {
        int t = __shfl_up_sync(0xFFFFFFFFu, inc, off);
        if (lane >= off) inc += t;
    }
    __shared__ int ws[8];
    if (lane == 31) ws[wid] = inc;
    __syncthreads();
    if (wid == 0 && lane < 8) {
        int x = ws[lane];
#pragma unroll
        for (int off = 1; off < 8; off <<= 1) {
            int t = __shfl_up_sync(0xFFu, x, off);
            if (lane >= off) x += t;
        }
        ws[lane] = x;
    }
    __syncthreads();
    int warpPre = (wid > 0) ? ws[wid - 1] : 0;
    if (tid < SCAN_G) g_bpre[tid] = warpPre + inc - v;
    if (tid == 0) g_rowptr[NN] = ws[7];
}

__global__ void __launch_bounds__(SCAN_B) k_writepre() {
    int i = blockIdx.x * SCAN_B + threadIdx.x;
    int lane = threadIdx.x & 31, wid = threadIdx.x >> 5;
    int v = (i < NN) ? g_count[i] : 0;
    int inc = v;
#pragma unroll
    for (int off = 1; off < 32; off <<= 1) {
        int t = __shfl_up_sync(0xFFFFFFFFu, inc, off);
        if (lane >= off) inc += t;
    }
    __shared__ int ws[8];
    if (lane == 31) ws[wid] = inc;
    __syncthreads();
    if (wid == 0 && lane < 8) {
        int x = ws[lane];
#pragma unroll
        for (int off = 1; off < 8; off <<= 1) {
            int t = __shfl_up_sync(0xFFu, x, off);
            if (lane >= off) x += t;
        }
        ws[lane] = x;
    }
    __syncthreads();
    int warpPre = (wid > 0) ? ws[wid - 1] : 0;
    if (i < NN) {
        int excl = g_bpre[blockIdx.x] + warpPre + inc - v;
        g_rowptr[i] = excl;
        g_cursor[i] = excl;
    }
}

__global__ void k_scatter(const int* __restrict__ ei, const float* __restrict__ ew) {
    int e = blockIdx.x * blockDim.x + threadIdx.x;
    if (e < NE) {
        int src = ei[e];
        int dst = ei[NE + e];
        int pos = atomicAdd(&g_cursor[dst], 1);
        g_col[pos]   = src;
        g_enorm[pos] = g_dis[src] * ew[e] * g_dis[dst];
    }
}

// ---------------- precision splits ----------------
__global__ void k_split2(const float* __restrict__ src, __nv_bfloat16* __restrict__ hi,
                         __nv_bfloat16* __restrict__ lo, int n) {
    int i = blockIdx.x * blockDim.x + threadIdx.x;
    if (i < n) {
        __nv_bfloat16 h, l;
        splitf(src[i], h, l);
        hi[i] = h; lo[i] = l;
    }
}

// W [fin][fout] fp32 -> Wt [fout][fin] bf16 hi/lo (transposed for mma row.col B)
__global__ void k_splitW(const float* __restrict__ W, __nv_bfloat16* __restrict__ whi,
                         __nv_bfloat16* __restrict__ wlo, int fin, int fout) {
    int idx = blockIdx.x * blockDim.x + threadIdx.x;
    if (idx < fin * fout) {
        int k = idx / fout, n = idx % fout;
        __nv_bfloat16 h, l;
        splitf(W[idx], h, l);
        whi[n * fin + k] = h;
        wlo[n * fin + k] = l;
    }
}

// ============ bf16-split tensor-core GEMM: C[M,FOUT] = A[M,FIN] @ W[FIN,FOUT] ============
// A given as bf16 hi/lo [M][FIN]; W given transposed bf16 hi/lo [FOUT][FIN].
// CTA: 128 rows x FOUT, 256 threads = 8 warps (4 M x 2 N). Warp tile 32 x FOUT/2.
// K staged in 64-chunks; SMEM rows padded to 36 u32 (conflict-free frag loads).
template <int FIN, int FOUT>
__global__ void __launch_bounds__(256) mma_gemm(const __nv_bfloat16* __restrict__ Ahi,
                                                const __nv_bfloat16* __restrict__ Alo,
                                                const __nv_bfloat16* __restrict__ Whi,
                                                const __nv_bfloat16* __restrict__ Wlo,
                                                float* __restrict__ C, int M) {
    constexpr int STR = 36;             // u32 per smem row (32 data + 4 pad)
    constexpr int NA  = FOUT / 16;      // n-atoms per warp (8 or 4)
    constexpr int NCH = FIN / 64;

    extern __shared__ uint32_t sm[];
    uint32_t* A_hi = sm;
    uint32_t* A_lo = sm + 128 * STR;
    uint32_t* B_hi = sm + 2 * 128 * STR;
    uint32_t* B_lo = B_hi + FOUT * STR;

    int tid = threadIdx.x;
    int lane = tid & 31, wid = tid >> 5;
    int warpM = wid & 3, warpN = wid >> 2;
    int q = lane & 3, r = lane >> 2;
    int rowBase = blockIdx.x * 128;
    int R0 = warpM * 32;
    int N0 = warpN * (FOUT / 2);

    float acc[2][NA][4];
#pragma unroll
    for (int ma = 0; ma < 2; ma++)
#pragma unroll
        for (int na = 0; na < NA; na++)
#pragma unroll
            for (int j = 0; j < 4; j++) acc[ma][na][j] = 0.0f;

    for (int ch = 0; ch < NCH; ch++) {
        int k0v = ch * 16;  // uint2 offset within a row (64 k / 4 per uint2)

        // stage A (hi+lo): 128 rows x 16 uint2 each
        for (int i = tid; i < 128 * 16; i += 256) {
            int row = i >> 4, c2 = i & 15;
            int grow = rowBase + row;
            uint2 vh = make_uint2(0u, 0u), vl = make_uint2(0u, 0u);
            if (grow < M) {
                vh = ((const uint2*)Ahi)[(size_t)grow * (FIN / 4) + k0v + c2];
                vl = ((const uint2*)Alo)[(size_t)grow * (FIN / 4) + k0v + c2];
            }
            *(uint2*)&A_hi[row * STR + c2 * 2] = vh;
            *(uint2*)&A_lo[row * STR + c2 * 2] = vl;
        }
        // stage B (hi+lo): FOUT rows x 16 uint2 each
        for (int i = tid; i < FOUT * 16; i += 256) {
            int n = i >> 4, c2 = i & 15;
            uint2 vh = ((const uint2*)Whi)[(size_t)n * (FIN / 4) + k0v + c2];
            uint2 vl = ((const uint2*)Wlo)[(size_t)n * (FIN / 4) + k0v + c2];
            *(uint2*)&B_hi[n * STR + c2 * 2] = vh;
            *(uint2*)&B_lo[n * STR + c2 * 2] = vl;
        }
        __syncthreads();

#pragma unroll
        for (int ks = 0; ks < 4; ks++) {
            uint32_t afh[2][4], afl[2][4];
#pragma unroll
            for (int ma = 0; ma < 2; ma++) {
                int rb = R0 + ma * 16 + r;
                const uint32_t* pa = &A_hi[rb * STR + ks * 8 + q];
                afh[ma][0] = pa[0];
                afh[ma][1] = pa[8 * STR];
                afh[ma][2] = pa[4];
                afh[ma][3] = pa[8 * STR + 4];
                const uint32_t* pl = &A_lo[rb * STR + ks * 8 + q];
                afl[ma][0] = pl[0];
                afl[ma][1] = pl[8 * STR];
                afl[ma][2] = pl[4];
                afl[ma][3] = pl[8 * STR + 4];
            }
#pragma unroll
            for (int na = 0; na < NA; na++) {
                int nb = N0 + na * 8 + r;
                uint32_t bh[2], bl[2];
                const uint32_t* pb = &B_hi[nb * STR + ks * 8 + q];
                bh[0] = pb[0]; bh[1] = pb[4];
                const uint32_t* pc = &B_lo[nb * STR + ks * 8 + q];
                bl[0] = pc[0]; bl[1] = pc[4];
#pragma unroll
                for (int ma = 0; ma < 2; ma++) {
                    mma_bf16(acc[ma][na], afh[ma], bh);
                    mma_bf16(acc[ma][na], afh[ma], bl);
                    mma_bf16(acc[ma][na], afl[ma], bh);
                }
            }
        }
        __syncthreads();
    }

    // epilogue: c0,c1 -> row, cols 2q,2q+1 ; c2,c3 -> row+8
#pragma unroll
    for (int ma = 0; ma < 2; ma++) {
#pragma unroll
        for (int na = 0; na < NA; na++) {
            int col = N0 + na * 8 + 2 * q;
            int row0 = rowBase + R0 + ma * 16 + r;
            if (row0 < M)
                *(float2*)&C[(size_t)row0 * FOUT + col] = make_float2(acc[ma][na][0], acc[ma][na][1]);
            int row1 = row0 + 8;
            if (row1 < M)
                *(float2*)&C[(size_t)row1 * FOUT + col] = make_float2(acc[ma][na][2], acc[ma][na][3]);
        }
    }
}

// ---------------- CSR aggregation: one warp per destination node ----------
// SPLIT: emit bf16 hi/lo (feeds next GEMM). Else: emit fp32.
template <int F, bool RELU, bool SPLIT>
__global__ void __launch_bounds__(256) agg_k(const float* __restrict__ h,
                                             const float* __restrict__ bias,
                                             float* __restrict__ outf,
                                             __nv_bfloat16* __restrict__ ohi,
                                             __nv_bfloat16* __restrict__ olo) {
    constexpr int TF = F / 32;
    int gw = (blockIdx.x * blockDim.x + threadIdx.x) >> 5;
    int lane = threadIdx.x & 31;
    if (gw >= NN) return;

    float acc[TF];
    float sn = g_selfn[gw];
#pragma unroll
    for (int j = 0; j < TF; j++) acc[j] = sn * h[(size_t)gw * F + j * 32 + lane];

    int beg = g_rowptr[gw];
    int end = g_rowptr[gw + 1];
    for (int e = beg; e < end; e++) {
        int s = g_col[e];
        float w = g_enorm[e];
        const float* hp = h + (size_t)s * F + lane;
#pragma unroll
        for (int j = 0; j < TF; j++) acc[j] = fmaf(w, __ldg(hp + j * 32), acc[j]);
    }

#pragma unroll
    for (int j = 0; j < TF; j++) {
        float v = acc[j] + bias[j * 32 + lane];
        if (RELU) v = fmaxf(v, 0.0f);
        if (SPLIT) {
            __nv_bfloat16 hh, ll;
            splitf(v, hh, ll);
            ohi[(size_t)gw * F + j * 32 + lane] = hh;
            olo[(size_t)gw * F + j * 32 + lane] = ll;
        } else {
            outf[(size_t)gw * F + j * 32 + lane] = v;
        }
    }
}

// ---------------- launch ----------------
extern "C" void kernel_launch(void* const* d_in, const int* in_sizes, int n_in,
                              void* d_out, int out_size) {
    const float* x  = (const float*)d_in[0];
    const int*   ei = (const int*)  d_in[1];
    const float* ew = (const float*)d_in[2];
    const float* W1 = (const float*)d_in[3];
    const float* b1 = (const float*)d_in[4];
    const float* W2 = (const float*)d_in[5];
    const float* b2 = (const float*)d_in[6];
    const float* W3 = (const float*)d_in[7];
    const float* b3 = (const float*)d_in[8];
    float* out = (float*)d_out;

    void *ph, *pxh, *pxl, *pah, *pal, *pwh, *pwl;
    cudaGetSymbolAddress(&ph,  g_h);
    cudaGetSymbolAddress(&pxh, g_xhi);
    cudaGetSymbolAddress(&pxl, g_xlo);
    cudaGetSymbolAddress(&pah, g_ahi);
    cudaGetSymbolAddress(&pal, g_alo);
    cudaGetSymbolAddress(&pwh, g_whi);
    cudaGetSymbolAddress(&pwl, g_wlo);
    float* h = (float*)ph;
    __nv_bfloat16* xhi = (__nv_bfloat16*)pxh;
    __nv_bfloat16* xlo = (__nv_bfloat16*)pxl;
    __nv_bfloat16* ahi = (__nv_bfloat16*)pah;
    __nv_bfloat16* alo = (__nv_bfloat16*)pal;
    __nv_bfloat16* whi = (__nv_bfloat16*)pwh;
    __nv_bfloat16* wlo = (__nv_bfloat16*)pwl;

    const int nodeBlocks = (NN + 255) / 256;
    const int edgeBlocks = (NE + 255) / 256;
    const int gemmBlocks = (NN + 127) / 128;  // 391
    const int aggBlocks  = (NN + 7) / 8;

    const int smem128 = (2 * 128 * 36 + 2 * 128 * 36) * 4;  // 73728
    const int smem64  = (2 * 128 * 36 + 2 * 64 * 36) * 4;   // 55296
    cudaFuncSetAttribute(mma_gemm<F0, F1>, cudaFuncAttributeMaxDynamicSharedMemorySize, smem128);
    cudaFuncSetAttribute(mma_gemm<F1, F2>, cudaFuncAttributeMaxDynamicSharedMemorySize, smem128);
    cudaFuncSetAttribute(mma_gemm<F2, F3>, cudaFuncAttributeMaxDynamicSharedMemorySize, smem64);

    // precision splits (independent of graph)
    k_split2<<<(NN * F0 + 255) / 256, 256>>>(x, xhi, xlo, NN * F0);
    k_splitW<<<(F0 * F1 + 255) / 256, 256>>>(W1, whi + W1T_OFF, wlo + W1T_OFF, F0, F1);
    k_splitW<<<(F1 * F2 + 255) / 256, 256>>>(W2, whi + W2T_OFF, wlo + W2T_OFF, F1, F2);
    k_splitW<<<(F2 * F3 + 255) / 256, 256>>>(W3, whi + W3T_OFF, wlo + W3T_OFF, F2, F3);

    // CSR build
    k_init<<<nodeBlocks, 256>>>();
    k_edge_deg<<<edgeBlocks, 256>>>(ei, ew);
    k_dis<<<nodeBlocks, 256>>>();
    k_blocksum<<<SCAN_G, SCAN_B>>>();
    k_scanbsum<<<1, SCAN_B>>>();
    k_writepre<<<SCAN_G, SCAN_B>>>();
    k_scatter<<<edgeBlocks, 256>>>(ei, ew);

    // Layer 1: 256 -> 128, relu, split output
    mma_gemm<F0, F1><<<gemmBlocks, 256, smem128>>>(xhi, xlo, whi + W1T_OFF, wlo + W1T_OFF, h, NN);
    agg_k<F1, true, true><<<aggBlocks, 256>>>(h, b1, nullptr, ahi, alo);

    // Layer 2: 128 -> 128, relu, split output
    mma_gemm<F1, F2><<<gemmBlocks, 256, smem128>>>(ahi, alo, whi + W2T_OFF, wlo + W2T_OFF, h, NN);
    agg_k<F2, true, true><<<aggBlocks, 256>>>(h, b2, nullptr, ahi, alo);

    // Layer 3: 128 -> 64, no relu, fp32 out
    mma_gemm<F2, F3><<<gemmBlocks, 256, smem64>>>(ahi, alo, whi + W3T_OFF, wlo + W3T_OFF, h, NN);
    agg_k<F3, false, false><<<aggBlocks, 256>>>(h, b3, out, nullptr, nullptr);
}

// round 8
// speedup vs baseline: 1.3846x; 1.0068x over previous
#include <cuda_runtime.h>
#include <cuda_bf16.h>
#include <cstdint>

// Problem constants (from reference setup_inputs)
#define NN 50000
#define NE 800000
#define F0 256
#define F1 128
#define F2 128
#define F3 64

#define SCAN_B 256
#define SCAN_G ((NN + SCAN_B - 1) / SCAN_B)   // 196

// transposed split weights: W1t [128][256] @0, W2t [128][128], W3t [64][128]
#define W1T_OFF 0
#define W2T_OFF (128 * 256)
#define W3T_OFF (128 * 256 + 128 * 128)
#define WSPL_TOT (128 * 256 + 128 * 128 + 64 * 128)   // 57344

// ---------------- device scratch (static, allocation-free) ----------------
__device__ float g_deg[NN];
__device__ float g_dis[NN];
__device__ float g_selfn[NN];
__device__ int   g_count[NN];
__device__ int   g_rowptr[NN + 1];
__device__ int   g_cursor[NN];
__device__ unsigned long long g_state[SCAN_G];   // lookback: flag(2b)<<62 | value
__device__ unsigned int g_ticket;
__device__ int   g_col[NE];
__device__ float g_enorm[NE];
__device__ float g_h[NN * 128];                  // GEMM output (fp32, agg input)
__device__ __nv_bfloat16 g_ahi[NN * 128];        // split agg outputs (layers 1,2)
__device__ __nv_bfloat16 g_alo[NN * 128];
__device__ __nv_bfloat16 g_whi[WSPL_TOT];
__device__ __nv_bfloat16 g_wlo[WSPL_TOT];

// ---------------- helpers ----------------
__device__ __forceinline__ void splitf(float v, __nv_bfloat16& h, __nv_bfloat16& l) {
    h = __float2bfloat16(v);
    l = __float2bfloat16(v - __bfloat162float(h));
}

__device__ __forceinline__ uint32_t packbf(__nv_bfloat16 a, __nv_bfloat16 b) {
    return (uint32_t)__bfloat16_as_ushort(a) | ((uint32_t)__bfloat16_as_ushort(b) << 16);
}

__device__ __forceinline__ void mma_bf16(float* c, const uint32_t* a, const uint32_t* b) {
    asm volatile(
        "mma.sync.aligned.m16n8k16.row.col.f32.bf16.bf16.f32 "
        "{%0,%1,%2,%3}, {%4,%5,%6,%7}, {%8,%9}, {%0,%1,%2,%3};"
        : "+f"(c[0]), "+f"(c[1]), "+f"(c[2]), "+f"(c[3])
        : "r"(a[0]), "r"(a[1]), "r"(a[2]), "r"(a[3]), "r"(b[0]), "r"(b[1]));
}

// ---------------- k_pre: weight splits (transposed) + init + scan-state reset ----
__global__ void __launch_bounds__(256) k_pre(const float* __restrict__ W1,
                                             const float* __restrict__ W2,
                                             const float* __restrict__ W3) {
    int t = blockIdx.x * 256 + threadIdx.x;
    if (t < WSPL_TOT) {
        const float* W; int fin, fout, off, idx;
        if (t < 128 * 256)            { W = W1; fin = F0; fout = F1; off = W1T_OFF; idx = t; }
        else if (t < W3T_OFF)         { W = W2; fin = F1; fout = F2; off = W2T_OFF; idx = t - W2T_OFF; }
        else                          { W = W3; fin = F2; fout = F3; off = W3T_OFF; idx = t - W3T_OFF; }
        int k = idx / fout, n = idx % fout;
        __nv_bfloat16 h, l;
        splitf(W[idx], h, l);
        g_whi[off + n * fin + k] = h;
        g_wlo[off + n * fin + k] = l;
    } else {
        int u = t - WSPL_TOT;
        if (u < NN) { g_deg[u] = 1.0f; g_count[u] = 0; }   // self-loop weight 1
        else {
            int s = u - NN;
            if (s < SCAN_G) g_state[s] = 0ULL;
            if (s == SCAN_G) g_ticket = 0u;
        }
    }
}

__global__ void k_edge_deg(const int* __restrict__ ei, const float* __restrict__ ew) {
    int e = blockIdx.x * blockDim.x + threadIdx.x;
    if (e < NE) {
        int d = ei[NE + e];
        atomicAdd(&g_deg[d], ew[e]);
        atomicAdd(&g_count[d], 1);
    }
}

// ---- single-pass decoupled-lookback scan, with dis/selfn fused ----
__global__ void __launch_bounds__(SCAN_B) k_scan_lb() {
    __shared__ unsigned int s_bid;
    if (threadIdx.x == 0) s_bid = atomicAdd(&g_ticket, 1u);
    __syncthreads();
    int bid = (int)s_bid;
    int i = bid * SCAN_B + threadIdx.x;
    int lane = threadIdx.x & 31, wid = threadIdx.x >> 5;

    // fused dis/selfn (g_deg final after k_edge_deg)
    if (i < NN) {
        float dg = g_deg[i];
        float dis = (dg > 0.0f) ? rsqrtf(dg) : 0.0f;
        g_dis[i] = dis;
        g_selfn[i] = dis * dis;
    }

    int v = (i < NN) ? g_count[i] : 0;
    int inc = v;
#pragma unroll
    for (int off = 1; off < 32; off <<= 1) {
        int t = __shfl_up_sync(0xFFFFFFFFu, inc, off);
        if (lane >= off) inc += t;
    }
    __shared__ int ws[8];
    if (lane == 31) ws[wid] = inc;
    __syncthreads();
    if (wid == 0 && lane < 8) {
        int x = ws[lane];
#pragma unroll
        for (int off = 1; off < 8; off <<= 1) {
            int t = __shfl_up_sync(0xFFu, x, off);
            if (lane >= off) x += t;
        }
        ws[lane] = x;
    }
    __syncthreads();
    int warpPre = (wid > 0) ? ws[wid - 1] : 0;
    int blockTotal = ws[7];

    __shared__ int s_prefix;
    if (threadIdx.x == 0) {
        int prefix = 0;
        if (bid == 0) {
            atomicExch(&g_state[0], (2ULL << 62) | (unsigned long long)(unsigned)blockTotal);
        } else {
            atomicExch(&g_state[bid], (1ULL << 62) | (unsigned long long)(unsigned)blockTotal);
            int j = bid - 1;
            while (true) {
                unsigned long long st = atomicAdd(&g_state[j], 0ULL);
                unsigned f = (unsigned)(st >> 62);
                if (f == 0u) continue;
                prefix += (int)(unsigned)(st & 0xFFFFFFFFULL);
                if (f == 2u) break;
                j--;
            }
            atomicExch(&g_state[bid],
                       (2ULL << 62) | (unsigned long long)(unsigned)(prefix + blockTotal));
        }
        s_prefix = prefix;
        if (bid == SCAN_G - 1) g_rowptr[NN] = prefix + blockTotal;
    }
    __syncthreads();
    int excl = s_prefix + warpPre + inc - v;
    if (i < NN) { g_rowptr[i] = excl; g_cursor[i] = excl; }
}

__global__ void k_scatter(const int* __restrict__ ei, const float* __restrict__ ew) {
    int e = blockIdx.x * blockDim.x + threadIdx.x;
    if (e < NE) {
        int src = ei[e];
        int dst = ei[NE + e];
        int pos = atomicAdd(&g_cursor[dst], 1);
        g_col[pos]   = src;
        g_enorm[pos] = g_dis[src] * ew[e] * g_dis[dst];
    }
}

// ============ bf16-split tensor-core GEMM: C[M,FOUT] = A[M,FIN] @ W[FIN,FOUT] ============
// ASPLIT: A is fp32 [M][FIN], split to bf16 hi/lo inline during staging.
// else:   A given as bf16 hi/lo [M][FIN] (Ap = hi, Alp = lo).
// W given transposed bf16 hi/lo [FOUT][FIN].
// CTA: 128 rows x FOUT, 256 threads = 8 warps (4 M x 2 N). Warp tile 32 x FOUT/2.
// K staged in 64-chunks; SMEM rows padded to 36 u32 (conflict-free frag loads).
template <int FIN, int FOUT, bool ASPLIT>
__global__ void __launch_bounds__(256) mma_gemm(const void* __restrict__ Ap,
                                                const void* __restrict__ Alp,
                                                const __nv_bfloat16* __restrict__ Whi,
                                                const __nv_bfloat16* __restrict__ Wlo,
                                                float* __restrict__ C, int M) {
    constexpr int STR = 36;             // u32 per smem row (32 data + 4 pad)
    constexpr int NA  = FOUT / 16;      // n-atoms per warp (8 or 4)
    constexpr int NCH = FIN / 64;

    extern __shared__ uint32_t sm[];
    uint32_t* A_hi = sm;
    uint32_t* A_lo = sm + 128 * STR;
    uint32_t* B_hi = sm + 2 * 128 * STR;
    uint32_t* B_lo = B_hi + FOUT * STR;

    int tid = threadIdx.x;
    int lane = tid & 31, wid = tid >> 5;
    int warpM = wid & 3, warpN = wid >> 2;
    int q = lane & 3, r = lane >> 2;
    int rowBase = blockIdx.x * 128;
    int R0 = warpM * 32;
    int N0 = warpN * (FOUT / 2);

    float acc[2][NA][4];
#pragma unroll
    for (int ma = 0; ma < 2; ma++)
#pragma unroll
        for (int na = 0; na < NA; na++)
#pragma unroll
            for (int j = 0; j < 4; j++) acc[ma][na][j] = 0.0f;

    for (int ch = 0; ch < NCH; ch++) {
        int k0v = ch * 16;  // uint2 offset within a row (64 k / 4 per uint2)

        // stage A (hi+lo): 128 rows x 16 uint2 each
        for (int i = tid; i < 128 * 16; i += 256) {
            int row = i >> 4, c2 = i & 15;
            int grow = rowBase + row;
            uint2 vh = make_uint2(0u, 0u), vl = make_uint2(0u, 0u);
            if (ASPLIT) {
                const float* A = (const float*)Ap;
                if (grow < M) {
                    float4 f = *(const float4*)&A[(size_t)grow * FIN + ch * 64 + c2 * 4];
                    __nv_bfloat16 h0, l0, h1, l1, h2, l2, h3, l3;
                    splitf(f.x, h0, l0); splitf(f.y, h1, l1);
                    splitf(f.z, h2, l2); splitf(f.w, h3, l3);
                    vh = make_uint2(packbf(h0, h1), packbf(h2, h3));
                    vl = make_uint2(packbf(l0, l1), packbf(l2, l3));
                }
            } else {
                if (grow < M) {
                    vh = ((const uint2*)Ap)[(size_t)grow * (FIN / 4) + k0v + c2];
                    vl = ((const uint2*)Alp)[(size_t)grow * (FIN / 4) + k0v + c2];
                }
            }
            *(uint2*)&A_hi[row * STR + c2 * 2] = vh;
            *(uint2*)&A_lo[row * STR + c2 * 2] = vl;
        }
        // stage B (hi+lo): FOUT rows x 16 uint2 each
        for (int i = tid; i < FOUT * 16; i += 256) {
            int n = i >> 4, c2 = i & 15;
            uint2 vh = ((const uint2*)Whi)[(size_t)n * (FIN / 4) + k0v + c2];
            uint2 vl = ((const uint2*)Wlo)[(size_t)n * (FIN / 4) + k0v + c2];
            *(uint2*)&B_hi[n * STR + c2 * 2] = vh;
            *(uint2*)&B_lo[n * STR + c2 * 2] = vl;
        }
        __syncthreads();

#pragma unroll
        for (int ks = 0; ks < 4; ks++) {
            uint32_t afh[2][4], afl[2][4];
#pragma unroll
            for (int ma = 0; ma < 2; ma++) {
                int rb = R0 + ma * 16 + r;
                const uint32_t* pa = &A_hi[rb * STR + ks * 8 + q];
                afh[ma][0] = pa[0];
                afh[ma][1] = pa[8 * STR];
                afh[ma][2] = pa[4];
                afh[ma][3] = pa[8 * STR + 4];
                const uint32_t* pl = &A_lo[rb * STR + ks * 8 + q];
                afl[ma][0] = pl[0];
                afl[ma][1] = pl[8 * STR];
                afl[ma][2] = pl[4];
                afl[ma][3] = pl[8 * STR + 4];
            }
#pragma unroll
            for (int na = 0; na < NA; na++) {
                int nb = N0 + na * 8 + r;
                uint32_t bh[2], bl[2];
                const uint32_t* pb = &B_hi[nb * STR + ks * 8 + q];
                bh[0] = pb[0]; bh[1] = pb[4];
                const uint32_t* pc = &B_lo[nb * STR + ks * 8 + q];
                bl[0] = pc[0]; bl[1] = pc[4];
#pragma unroll
                for (int ma = 0; ma < 2; ma++) {
                    mma_bf16(acc[ma][na], afh[ma], bh);
                    mma_bf16(acc[ma][na], afh[ma], bl);
                    mma_bf16(acc[ma][na], afl[ma], bh);
                }
            }
        }
        __syncthreads();
    }

    // epilogue: c0,c1 -> row, cols 2q,2q+1 ; c2,c3 -> row+8
#pragma unroll
    for (int ma = 0; ma < 2; ma++) {
#pragma unroll
        for (int na = 0; na < NA; na++) {
            int col = N0 + na * 8 + 2 * q;
            int row0 = rowBase + R0 + ma * 16 + r;
            if (row0 < M)
                *(float2*)&C[(size_t)row0 * FOUT + col] = make_float2(acc[ma][na][0], acc[ma][na][1]);
            int row1 = row0 + 8;
            if (row1 < M)
                *(float2*)&C[(size_t)row1 * FOUT + col] = make_float2(acc[ma][na][2], acc[ma][na][3]);
        }
    }
}

// ---------------- CSR aggregation: one warp per destination node ----------
// SPLIT: emit bf16 hi/lo (feeds next GEMM). Else: emit fp32.
template <int F, bool RELU, bool SPLIT>
__global__ void __launch_bounds__(256) agg_k(const float* __restrict__ h,
                                             const float* __restrict__ bias,
                                             float* __restrict__ outf,
                                             __nv_bfloat16* __restrict__ ohi,
                                             __nv_bfloat16* __restrict__ olo) {
    constexpr int TF = F / 32;
    int gw = (blockIdx.x * blockDim.x + threadIdx.x) >> 5;
    int lane = threadIdx.x & 31;
    if (gw >= NN) return;

    float acc[TF];
    float sn = g_selfn[gw];
#pragma unroll
    for (int j = 0; j < TF; j++) acc[j] = sn * h[(size_t)gw * F + j * 32 + lane];

    int beg = g_rowptr[gw];
    int end = g_rowptr[gw + 1];
    for (int e = beg; e < end; e++) {
        int s = g_col[e];
        float w = g_enorm[e];
        const float* hp = h + (size_t)s * F + lane;
#pragma unroll
        for (int j = 0; j < TF; j++) acc[j] = fmaf(w, __ldg(hp + j * 32), acc[j]);
    }

#pragma unroll
    for (int j = 0; j < TF; j++) {
        float v = acc[j] + bias[j * 32 + lane];
        if (RELU) v = fmaxf(v, 0.0f);
        if (SPLIT) {
            __nv_bfloat16 hh, ll;
            splitf(v, hh, ll);
            ohi[(size_t)gw * F + j * 32 + lane] = hh;
            olo[(size_t)gw * F + j * 32 + lane] = ll;
        } else {
            outf[(size_t)gw * F + j * 32 + lane] = v;
        }
    }
}

// ---------------- launch ----------------
extern "C" void kernel_launch(void* const* d_in, const int* in_sizes, int n_in,
                              void* d_out, int out_size) {
    const float* x  = (const float*)d_in[0];
    const int*   ei = (const int*)  d_in[1];
    const float* ew = (const float*)d_in[2];
    const float* W1 = (const float*)d_in[3];
    const float* b1 = (const float*)d_in[4];
    const float* W2 = (const float*)d_in[5];
    const float* b2 = (const float*)d_in[6];
    const float* W3 = (const float*)d_in[7];
    const float* b3 = (const float*)d_in[8];
    float* out = (float*)d_out;

    void *ph, *pah, *pal, *pwh, *pwl;
    cudaGetSymbolAddress(&ph,  g_h);
    cudaGetSymbolAddress(&pah, g_ahi);
    cudaGetSymbolAddress(&pal, g_alo);
    cudaGetSymbolAddress(&pwh, g_whi);
    cudaGetSymbolAddress(&pwl, g_wlo);
    float* h = (float*)ph;
    __nv_bfloat16* ahi = (__nv_bfloat16*)pah;
    __nv_bfloat16* alo = (__nv_bfloat16*)pal;
    __nv_bfloat16* whi = (__nv_bfloat16*)pwh;
    __nv_bfloat16* wlo = (__nv_bfloat16*)pwl;

    const int preBlocks  = (WSPL_TOT + NN + SCAN_G + 1 + 255) / 256;
    const int edgeBlocks = (NE + 255) / 256;
    const int gemmBlocks = (NN + 127) / 128;  // 391
    const int aggBlocks  = (NN + 7) / 8;

    const int smem128 = (2 * 128 * 36 + 2 * 128 * 36) * 4;  // 73728
    const int smem64  = (2 * 128 * 36 + 2 * 64 * 36) * 4;   // 55296
    cudaFuncSetAttribute(mma_gemm<F0, F1, true>,  cudaFuncAttributeMaxDynamicSharedMemorySize, smem128);
    cudaFuncSetAttribute(mma_gemm<F1, F2, false>, cudaFuncAttributeMaxDynamicSharedMemorySize, smem128);
    cudaFuncSetAttribute(mma_gemm<F2, F3, false>, cudaFuncAttributeMaxDynamicSharedMemorySize, smem64);

    // 0: weight splits + init + scan-state reset
    k_pre<<<preBlocks, 256>>>(W1, W2, W3);
    // 1: degrees + counts
    k_edge_deg<<<edgeBlocks, 256>>>(ei, ew);
    // 2: single-pass scan (+ dis/selfn)
    k_scan_lb<<<SCAN_G, SCAN_B>>>();
    // 3: CSR scatter
    k_scatter<<<edgeBlocks, 256>>>(ei, ew);

    // 4-5: Layer 1: 256 -> 128, relu, split output (A split fused into GEMM)
    mma_gemm<F0, F1, true><<<gemmBlocks, 256, smem128>>>(x, nullptr, whi + W1T_OFF, wlo + W1T_OFF, h, NN);
    agg_k<F1, true, true><<<aggBlocks, 256>>>(h, b1, nullptr, ahi, alo);

    // 6-7: Layer 2: 128 -> 128, relu, split output
    mma_gemm<F1, F2, false><<<gemmBlocks, 256, smem128>>>(ahi, alo, whi + W2T_OFF, wlo + W2T_OFF, h, NN);
    agg_k<F2, true, true><<<aggBlocks, 256>>>(h, b2, nullptr, ahi, alo);

    // 8-9: Layer 3: 128 -> 64, no relu, fp32 out
    mma_gemm<F2, F3, false><<<gemmBlocks, 256, smem64>>>(ahi, alo, whi + W3T_OFF, wlo + W3T_OFF, h, NN);
    agg_k<F3, false, false><<<aggBlocks, 256>>>(h, b3, out, nullptr, nullptr);
}